// round 17
// baseline (speedup 1.0000x reference)
#include <cuda_runtime.h>

#define NN 100000
#define EE 500000
#define DD 128
#define RR 10
#define EPS 1e-5f

#define BUCK_SH 8
#define NBUCK ((NN + 255) >> BUCK_SH)          // 391
#define NBLK  200
#define CHUNK ((EE + NBLK - 1) / NBLK)         // 2500
#define GEMM_TILES ((NN + 127) / 128)          // 782

typedef unsigned long long u64;
typedef unsigned int u32;

// ---------------- scratch (device globals; no allocation allowed) ----------
__device__ float g_agg_in [NN * DD];
__device__ float g_agg_out[NN * DD];
__device__ float g_out    [NN * DD];
__device__ float g_x      [NN * DD];
__device__ float g_stats  [2][2 * DD];
__device__ float g_r1     [RR * DD];
__device__ u32   g_wtf    [3][DD][DD];   // per-layer tf32 weights (loop folded)

__device__ int   g_bhist [2][NBUCK][NBLK];
__device__ int   g_bpre  [2][NBUCK][NBLK];
__device__ int   g_btot  [2][NBUCK];
__device__ int   g_bstart[2][NBUCK + 1];
__device__ int   g_ebuf  [2][EE];    // (local<<21)|(type<<17)|nbr
__device__ int   g_off   [2][NN + 1];
__device__ float g_dinv  [2][NN];
__device__ int   g_nbr   [2][EE];    // (type<<17)|nbr

__device__ unsigned g_barc = 0;
__device__ unsigned g_barg = 0;

// ---------------- helpers ---------------------------------------------------
__device__ __forceinline__ float fast_tanh(float x) {
    float e = __expf(2.0f * x);
    return __fdividef(e - 1.0f, e + 1.0f);
}
__device__ __forceinline__ u32 f2tf(float f) {
    u32 u; asm("cvt.rna.tf32.f32 %0, %1;" : "=r"(u) : "f"(f)); return u;
}
__device__ __forceinline__ void mma_tf32(float* c, const u32* a, u32 b0, u32 b1) {
    asm volatile(
        "mma.sync.aligned.m16n8k8.row.col.f32.tf32.tf32.f32 "
        "{%0,%1,%2,%3},{%4,%5,%6,%7},{%8,%9},{%0,%1,%2,%3};"
        : "+f"(c[0]), "+f"(c[1]), "+f"(c[2]), "+f"(c[3])
        : "r"(a[0]), "r"(a[1]), "r"(a[2]), "r"(a[3]), "r"(b0), "r"(b1));
}

// grid-wide barrier: all blocks resident (grid sized by occupancy API)
__device__ __forceinline__ void gbar() {
    __syncthreads();
    if (threadIdx.x == 0) {
        __threadfence();
        unsigned gen = atomicAdd(&g_barg, 0u);
        if (atomicAdd(&g_barc, 1u) == gridDim.x - 1u) {
            atomicExch(&g_barc, 0u);
            __threadfence();
            atomicAdd(&g_barg, 1u);
        } else {
            while (atomicAdd(&g_barg, 0u) == gen) __nanosleep(200);
        }
        __threadfence();
    }
    __syncthreads();
}

// ---------------- the whole pipeline in one kernel --------------------------
__global__ __launch_bounds__(256, 2)
void k_fused(const float* __restrict__ x0, const float* __restrict__ r0,
             const float* __restrict__ w_in, const float* __restrict__ w_out,
             const float* __restrict__ w_loop, const float* __restrict__ w_rel,
             const float* __restrict__ loop_rel, const float* __restrict__ bias,
             const int* __restrict__ esrc, const int* __restrict__ edst,
             const int* __restrict__ etyp,
             float* __restrict__ x_final, float* __restrict__ r_final) {
    __shared__ __align__(16) unsigned char SU[49152];   // 48 KB union
    const int tid = threadIdx.x;
    const int NB = gridDim.x;

    // ===== Phase 0: bucket histograms + zero stats ==========================
    {
        int* bins = (int*)SU;
        if (blockIdx.x == 0)
            for (int i = tid; i < 4 * DD; i += 256) ((float*)g_stats)[i] = 0.f;
        for (int vb = blockIdx.x; vb < 2 * NBLK; vb += NB) {
            int dir = vb / NBLK, b = vb % NBLK;
            const int* __restrict__ key = dir ? edst : esrc;
            __syncthreads();
            for (int i = tid; i < NBUCK; i += 256) bins[i] = 0;
            __syncthreads();
            int beg = b * CHUNK, end = min(beg + CHUNK, EE);
            for (int e = beg + tid; e < end; e += 256)
                atomicAdd(&bins[key[e] >> BUCK_SH], 1);
            __syncthreads();
            for (int i = tid; i < NBUCK; i += 256)
                g_bhist[dir][i][b] = bins[i];
        }
    }
    gbar();

    // ===== Phase 1: per-bucket scan over blocks =============================
    {
        int* sm = (int*)SU;
        for (int vb = blockIdx.x; vb < 2 * NBUCK; vb += NB) {
            int dir = vb / NBUCK, bu = vb % NBUCK;
            __syncthreads();
            int v = (tid < NBLK) ? g_bhist[dir][bu][tid] : 0;
            sm[tid] = v;
            __syncthreads();
            for (int o = 1; o < 256; o <<= 1) {
                int u = (tid >= o) ? sm[tid - o] : 0;
                __syncthreads();
                sm[tid] += u;
                __syncthreads();
            }
            if (tid < NBLK) g_bpre[dir][bu][tid] = sm[tid] - v;
            if (tid == 255) g_btot[dir][bu] = sm[255];
        }
    }
    gbar();

    // ===== Phase 2: top scan over buckets (block 0) =========================
    if (blockIdx.x == 0) {
        int* sm = (int*)SU;
        for (int dir = 0; dir < 2; dir++) {
            int e0 = 2 * tid, e1 = 2 * tid + 1;
            int v0 = (e0 < NBUCK) ? g_btot[dir][e0] : 0;
            int v1 = (e1 < NBUCK) ? g_btot[dir][e1] : 0;
            int p = v0 + v1;
            __syncthreads();
            sm[tid] = p;
            __syncthreads();
            for (int o = 1; o < 256; o <<= 1) {
                int u = (tid >= o) ? sm[tid - o] : 0;
                __syncthreads();
                sm[tid] += u;
                __syncthreads();
            }
            int excl = sm[tid] - p;
            if (e0 < NBUCK) g_bstart[dir][e0] = excl;
            if (e1 < NBUCK) g_bstart[dir][e1] = excl + v0;
        }
        if (tid == 0) {
            g_bstart[0][NBUCK] = EE; g_bstart[1][NBUCK] = EE;
            g_off[0][NN] = EE; g_off[1][NN] = EE;
        }
    }
    gbar();

    // ===== Phase 3: scatter into buckets ====================================
    {
        int* cur = (int*)SU;
        for (int vb = blockIdx.x; vb < 2 * NBLK; vb += NB) {
            int dir = vb / NBLK, b = vb % NBLK;
            const int* __restrict__ key = dir ? edst : esrc;
            const int* __restrict__ oth = dir ? esrc : edst;
            __syncthreads();
            for (int i = tid; i < NBUCK; i += 256)
                cur[i] = g_bstart[dir][i] + g_bpre[dir][i][b];
            __syncthreads();
            int beg = b * CHUNK, end = min(beg + CHUNK, EE);
            for (int e = beg + tid; e < end; e += 256) {
                int k = key[e];
                int pos = atomicAdd(&cur[k >> BUCK_SH], 1);
                g_ebuf[dir][pos] = ((k & 255) << 21) | (etyp[e] << 17) | oth[e];
            }
        }
    }
    gbar();

    // ===== Phase 4: finalize CSR per bucket =================================
    {
        int* cnt = (int*)SU;
        int* pre = cnt + 256;
        for (int vb = blockIdx.x; vb < 2 * NBUCK; vb += NB) {
            int dir = vb / NBUCK, bu = vb % NBUCK;
            int beg = g_bstart[dir][bu], end = g_bstart[dir][bu + 1];
            __syncthreads();
            cnt[tid] = 0;
            __syncthreads();
            for (int p = beg + tid; p < end; p += 256)
                atomicAdd(&cnt[g_ebuf[dir][p] >> 21], 1);
            __syncthreads();
            int v = cnt[tid];
            pre[tid] = v;
            __syncthreads();
            for (int o = 1; o < 256; o <<= 1) {
                int u = (tid >= o) ? pre[tid - o] : 0;
                __syncthreads();
                pre[tid] += u;
                __syncthreads();
            }
            int excl = pre[tid] - v;
            int node = (bu << BUCK_SH) + tid;
            if (node < NN) {
                g_off[dir][node] = beg + excl;
                g_dinv[dir][node] = (v > 0) ? rsqrtf((float)v) : 0.0f;
            }
            __syncthreads();
            cnt[tid] = excl;
            __syncthreads();
            for (int p = beg + tid; p < end; p += 256) {
                int e = g_ebuf[dir][p];
                int pos = beg + atomicAdd(&cnt[e >> 21], 1);
                g_nbr[dir][pos] = e & 0x1FFFFF;
            }
        }
    }
    gbar();

    // ===== Layers ===========================================================
    for (int l = 0; l < 2; l++) {
        const float* xin = l ? g_x : x0;
        const float* rin = l ? g_r1 : r0;
        const float* B0 = w_in  + l * DD * DD;
        const float* B1 = w_out + l * DD * DD;
        const float* B2w = w_loop + l * DD * DD;
        const float* lr = loop_rel + l * DD;
        const float* bi = bias + l * DD;
        float* xout = l ? x_final : g_x;
        float* rout = l ? r_final : g_r1;

        // ---- weight pre-convert (tf32, loop_rel folded) + aggregation ----
        {
            // pre-convert this layer's weights (grid-stride, tiny)
            for (int idx = blockIdx.x * 256 + tid; idx < 3 * DD * DD; idx += NB * 256) {
                int c = idx >> 14;
                int rem = idx & 16383;
                int k = rem >> 7, col = rem & 127;
                const float* W = (c == 0) ? B0 : (c == 1) ? B1 : B2w;
                float v = W[k * DD + col];
                if (c == 2) v *= lr[k];
                g_wtf[c][k][col] = f2tf(v);
            }

            float* rs = (float*)SU;
            for (int i = tid; i < RR * DD; i += 256) rs[i] = rin[i];
            __syncthreads();
            int wid = tid >> 5, lane = tid & 31;
            const float4* x4 = (const float4*)xin;
            const int* __restrict__ nbr0 = g_nbr[0];
            const int* __restrict__ nbr1 = g_nbr[1];
            const float* __restrict__ dv0p = g_dinv[0];
            const float* __restrict__ dv1p = g_dinv[1];

            // one warp handles BOTH directions of node n -> 8 gathers in flight
            for (int n = blockIdx.x * 8 + wid; n < NN; n += NB * 8) {
                int p0 = g_off[0][n], e0 = g_off[0][n + 1];
                int p1 = g_off[1][n], e1 = g_off[1][n + 1];
                float4 acc0 = make_float4(0.f, 0.f, 0.f, 0.f);
                float4 acc1 = make_float4(0.f, 0.f, 0.f, 0.f);
                int len = max(e0 - p0, e1 - p1);
                for (int t = 0; t < len; t += 4) {
                    int mA[4], mB[4], tA[4], tB[4];
                    float dA[4], dB[4];
#pragma unroll
                    for (int j = 0; j < 4; j++) {
                        int pa = p0 + t + j, pb = p1 + t + j;
                        int pkA = nbr0[min(pa, EE - 1)];
                        int pkB = nbr1[min(pb, EE - 1)];
                        mA[j] = pkA & 0x1FFFF; tA[j] = pkA >> 17;
                        mB[j] = pkB & 0x1FFFF; tB[j] = pkB >> 17;
                        dA[j] = (pa < e0) ? dv0p[mA[j]] : 0.f;
                        dB[j] = (pb < e1) ? dv1p[mB[j]] : 0.f;
                    }
#pragma unroll
                    for (int j = 0; j < 4; j++) {
                        if (p0 + t + j < e0) {           // warp-uniform branch
                            float4 xv = x4[mA[j] * 32 + lane];
                            float4 rv = *(const float4*)&rs[tA[j] * DD + lane * 4];
                            acc0.x += dA[j] * xv.x * rv.x;
                            acc0.y += dA[j] * xv.y * rv.y;
                            acc0.z += dA[j] * xv.z * rv.z;
                            acc0.w += dA[j] * xv.w * rv.w;
                        }
                        if (p1 + t + j < e1) {
                            float4 xv = x4[mB[j] * 32 + lane];
                            float4 rv = *(const float4*)&rs[tB[j] * DD + lane * 4];
                            acc1.x += dB[j] * xv.x * rv.x;
                            acc1.y += dB[j] * xv.y * rv.y;
                            acc1.z += dB[j] * xv.z * rv.z;
                            acc1.w += dB[j] * xv.w * rv.w;
                        }
                    }
                }
                float o0 = dv0p[n], o1 = dv1p[n];
                acc0.x *= o0; acc0.y *= o0; acc0.z *= o0; acc0.w *= o0;
                acc1.x *= o1; acc1.y *= o1; acc1.z *= o1; acc1.w *= o1;
                *(float4*)&g_agg_in [(size_t)n * DD + lane * 4] = acc0;
                *(float4*)&g_agg_out[(size_t)n * DD + lane * 4] = acc1;
            }
        }
        gbar();

        // ---- GEMM via tf32 mma.sync + bias + BN partial stats ----
        {
            u32 (*A_s)[36]  = (u32(*)[36])SU;                    // 18432 B
            u32 (*B_s)[136] = (u32(*)[136])(SU + 128 * 36 * 4);  // 17408 B
            const int lane = tid & 31, wid = tid >> 5;
            const int wr = wid >> 1, wc = wid & 1;   // warp 32x64 tile
            const int qr = lane >> 2, qc = lane & 3;

            for (int tile = blockIdx.x; tile < GEMM_TILES; tile += NB) {
                const int rowBase = tile * 128;
                float C[2][8][4];
#pragma unroll
                for (int m = 0; m < 2; m++)
#pragma unroll
                    for (int n = 0; n < 8; n++)
#pragma unroll
                        for (int j = 0; j < 4; j++) C[m][n][j] = 0.f;

                for (int c = 0; c < 3; c++) {
                    const float* A = (c == 0) ? g_agg_in : (c == 1) ? g_agg_out : xin;
                    for (int ks = 0; ks < 4; ks++) {
                        __syncthreads();
                        {   // stage A: 128 rows x 32 k, cvt to tf32
                            int k4 = tid & 7;
                            int r0i = tid >> 3;
#pragma unroll
                            for (int rr = 0; rr < 4; rr++) {
                                int row = r0i + rr * 32;
                                int grow = rowBase + row;
                                float4 v = make_float4(0.f, 0.f, 0.f, 0.f);
                                if (grow < NN)
                                    v = *(const float4*)&A[(size_t)grow * DD + ks * 32 + k4 * 4];
                                uint4 w = make_uint4(f2tf(v.x), f2tf(v.y), f2tf(v.z), f2tf(v.w));
                                *(uint4*)&A_s[row][k4 * 4] = w;
                            }
                        }
                        {   // stage B: raw copy of pre-converted tf32 weights
                            int c4 = tid & 31;
                            int k0 = tid >> 5;
#pragma unroll
                            for (int p = 0; p < 4; p++) {
                                int kk = k0 + p * 8;
                                int gk = ks * 32 + kk;
                                uint4 w = *(const uint4*)&g_wtf[c][gk][c4 * 4];
                                *(uint4*)&B_s[kk][c4 * 4] = w;
                            }
                        }
                        __syncthreads();
#pragma unroll
                        for (int kk = 0; kk < 32; kk += 8) {
                            u32 a[2][4];
#pragma unroll
                            for (int m = 0; m < 2; m++) {
                                int r = wr * 32 + m * 16 + qr;
                                a[m][0] = A_s[r][kk + qc];
                                a[m][1] = A_s[r + 8][kk + qc];
                                a[m][2] = A_s[r][kk + qc + 4];
                                a[m][3] = A_s[r + 8][kk + qc + 4];
                            }
#pragma unroll
                            for (int n = 0; n < 8; n++) {
                                int cl = wc * 64 + n * 8 + qr;
                                u32 b0 = B_s[kk + qc][cl];
                                u32 b1 = B_s[kk + qc + 4][cl];
                                mma_tf32(C[0][n], a[0], b0, b1);
                                mma_tf32(C[1][n], a[1], b0, b1);
                            }
                        }
                    }
                }

                // epilogue: /3 + bias + store + BN partial stats
                const float third = 1.0f / 3.0f;
                float scol[16], qcol[16];
#pragma unroll
                for (int j = 0; j < 16; j++) { scol[j] = 0.f; qcol[j] = 0.f; }
#pragma unroll
                for (int m = 0; m < 2; m++) {
#pragma unroll
                    for (int n = 0; n < 8; n++) {
                        int col = wc * 64 + n * 8 + qc * 2;
                        float b0v = bi[col], b1v = bi[col + 1];
                        int ra = rowBase + wr * 32 + m * 16 + qr;
                        int rb = ra + 8;
                        float lo0 = C[m][n][0] * third + b0v;
                        float hi0 = C[m][n][1] * third + b1v;
                        float lo1 = C[m][n][2] * third + b0v;
                        float hi1 = C[m][n][3] * third + b1v;
                        if (ra < NN) {
                            *(float2*)&g_out[(size_t)ra * DD + col] = make_float2(lo0, hi0);
                            scol[n * 2]     += lo0; qcol[n * 2]     += lo0 * lo0;
                            scol[n * 2 + 1] += hi0; qcol[n * 2 + 1] += hi0 * hi0;
                        }
                        if (rb < NN) {
                            *(float2*)&g_out[(size_t)rb * DD + col] = make_float2(lo1, hi1);
                            scol[n * 2]     += lo1; qcol[n * 2]     += lo1 * lo1;
                            scol[n * 2 + 1] += hi1; qcol[n * 2 + 1] += hi1 * hi1;
                        }
                    }
                }

                __syncthreads();
                float* ssum = (float*)SU;
                float* ssq  = ssum + DD;
                if (tid < DD) { ssum[tid] = 0.f; ssq[tid] = 0.f; }
                __syncthreads();
#pragma unroll
                for (int n = 0; n < 8; n++) {
#pragma unroll
                    for (int b = 0; b < 2; b++) {
                        int col = wc * 64 + n * 8 + qc * 2 + b;
                        atomicAdd(&ssum[col], scol[n * 2 + b]);
                        atomicAdd(&ssq[col], qcol[n * 2 + b]);
                    }
                }
                __syncthreads();
                if (tid < DD) {
                    atomicAdd(&g_stats[l][tid], ssum[tid]);
                    atomicAdd(&g_stats[l][DD + tid], ssq[tid]);
                }
                __syncthreads();
            }
        }
        gbar();

        // ---- BN normalize + tanh, and relation transform (grid-wide) ----
        {
            int cg = tid & 31;
            int rr = tid >> 5;
            int c0 = cg * 4;
            const float invN = 1.0f / NN;
            float m0 = g_stats[l][c0] * invN,     m1 = g_stats[l][c0 + 1] * invN;
            float m2 = g_stats[l][c0 + 2] * invN, m3 = g_stats[l][c0 + 3] * invN;
            float i0 = rsqrtf(g_stats[l][DD + c0] * invN - m0 * m0 + EPS);
            float i1 = rsqrtf(g_stats[l][DD + c0 + 1] * invN - m1 * m1 + EPS);
            float i2 = rsqrtf(g_stats[l][DD + c0 + 2] * invN - m2 * m2 + EPS);
            float i3 = rsqrtf(g_stats[l][DD + c0 + 3] * invN - m3 * m3 + EPS);
            // relation transform: distributed grid-wide (first ~5 blocks)
            for (int idx = blockIdx.x * 256 + tid; idx < RR * DD; idx += NB * 256) {
                int i = idx / DD, j = idx % DD;
                const float* wr2 = w_rel + l * DD * DD;
                float s = 0.f;
                for (int k = 0; k < DD; k++)
                    s += rin[i * DD + k] * wr2[k * DD + j];
                rout[idx] = s;
            }
            for (int n = blockIdx.x * 8 + rr; n < NN; n += NB * 8) {
                float4 v = *(const float4*)&g_out[(size_t)n * DD + c0];
                v.x = fast_tanh((v.x - m0) * i0);
                v.y = fast_tanh((v.y - m1) * i1);
                v.z = fast_tanh((v.z - m2) * i2);
                v.w = fast_tanh((v.w - m3) * i3);
                *(float4*)&xout[(size_t)n * DD + c0] = v;
            }
        }
        gbar();
    }
}

// ---------------- launch ----------------------------------------------------
extern "C" void kernel_launch(void* const* d_in, const int* in_sizes, int n_in,
                              void* d_out, int out_size) {
    const float* x0       = (const float*)d_in[0];
    const float* r0       = (const float*)d_in[1];
    const float* w_in     = (const float*)d_in[2];
    const float* w_out    = (const float*)d_in[3];
    const float* w_loop   = (const float*)d_in[4];
    const float* w_rel    = (const float*)d_in[5];
    const float* loop_rel = (const float*)d_in[6];
    const float* bias     = (const float*)d_in[7];
    const int*   esrc     = (const int*)d_in[8];
    const int*   edst     = (const int*)d_in[9];
    const int*   etyp     = (const int*)d_in[10];

    float* out     = (float*)d_out;
    float* x_final = out;
    float* r_final = out + (size_t)NN * DD;

    int dev = 0;
    cudaGetDevice(&dev);
    int sms = 148;
    cudaDeviceGetAttribute(&sms, cudaDevAttrMultiProcessorCount, dev);
    int occ = 1;
    cudaOccupancyMaxActiveBlocksPerMultiprocessor(&occ, k_fused, 256, 0);
    if (occ < 1) occ = 1;
    int grid = sms * occ;

    k_fused<<<grid, 256>>>(x0, r0, w_in, w_out, w_loop, w_rel, loop_rel, bias,
                           esrc, edst, etyp, x_final, r_final);
}